// round 15
// baseline (speedup 1.0000x reference)
#include <cuda_runtime.h>
#include <cuda_bf16.h>
#include <cstdint>

// ---------------------------------------------------------------------------
// GeneInteractionDango v14: v13 (3 blocks/SM, 76.8KB smem, 168 regs) +
//  (1) fused Q+K GEMM pass (one A-ldmatrix stream, two accumulators)
//  (2) attention phase widened to 128 threads (d-half split + shfl reduce).
// L1-traffic model: A*4+B per pass; QK fusion removes one A*4 per layer.
// ---------------------------------------------------------------------------

#define GROUPS   131072
#define SEQ      3
#define H        128
#define GPB      16
#define TPB      48
#define NTHREADS 128

#define XSTR     132      // f32 row stride (words)
#define RB       272u     // bf16 row stride bytes (ldsm-safe)
#define QRB      256u     // Qb row stride bytes (swizzled, non-ldsm)

// smem byte offsets (total 76800)
#define XS_OFF   0        // f32 [48][132] = 25344 (tail reused as sSc)
#define AB_OFF   25344    // bf16 [48][136] = 13056
#define KB_OFF   38400
#define VB_OFF   51456
#define QB_OFF   64512    // bf16 [48][128] swizzled = 12288
#define SMEM_SZ  76800

typedef unsigned long long u64;

// frag images: 0-7 = {Wq,Wk,Wv,Wo} x layer ; 8 = Ws hi ; 9 = Ws lo
__device__ __align__(16) u64 g_frag[10 * 8 * 16 * 32];

__device__ __forceinline__ void mma_bf16(float* c,
                                         uint32_t a0, uint32_t a1, uint32_t a2, uint32_t a3,
                                         uint32_t b0, uint32_t b1)
{
    asm volatile(
        "mma.sync.aligned.m16n8k16.row.col.f32.bf16.bf16.f32 "
        "{%0,%1,%2,%3}, {%4,%5,%6,%7}, {%8,%9}, {%0,%1,%2,%3};"
        : "+f"(c[0]), "+f"(c[1]), "+f"(c[2]), "+f"(c[3])
        : "r"(a0), "r"(a1), "r"(a2), "r"(a3), "r"(b0), "r"(b1));
}

__device__ __forceinline__ void ldsm_x4(uint32_t& r0, uint32_t& r1, uint32_t& r2, uint32_t& r3,
                                        uint32_t addr)
{
    asm volatile("ldmatrix.sync.aligned.m8n8.x4.shared.b16 {%0,%1,%2,%3}, [%4];"
                 : "=r"(r0), "=r"(r1), "=r"(r2), "=r"(r3) : "r"(addr));
}

__device__ __forceinline__ uint32_t smem_u32(const void* p) {
    uint32_t a;
    asm("{ .reg .u64 t; cvta.to.shared.u64 t, %1; cvt.u32.u64 %0, t; }" : "=r"(a) : "l"(p));
    return a;
}

__device__ __forceinline__ uint32_t bf16x2(float a, float b) {
    __nv_bfloat162 v = __floats2bfloat162_rn(a, b);
    return *(uint32_t*)&v;
}

// streaming-A GEMM: [48x128]@[128x32] per warp; A via ldmatrix, B via LDG
__device__ __forceinline__ void gemm3g(uint32_t aBase, uint32_t aoff,
                                       const u64* __restrict__ fb,
                                       float acc[3][4][4])
{
    u64 cur[4];
#pragma unroll
    for (int j = 0; j < 4; j++) cur[j] = __ldg(fb + j * 32);
#pragma unroll
    for (int ks = 0; ks < 8; ks++) {
        uint32_t a[3][4];
#pragma unroll
        for (int s = 0; s < 3; s++)
            ldsm_x4(a[s][0], a[s][1], a[s][2], a[s][3],
                    aBase + (uint32_t)s * (16u * RB) + aoff + (uint32_t)ks * 32u);
        u64 nxt[4];
        if (ks < 7) {
#pragma unroll
            for (int j = 0; j < 4; j++) nxt[j] = __ldg(fb + (ks + 1) * 512 + j * 32);
        }
#pragma unroll
        for (int s = 0; s < 3; s++)
#pragma unroll
            for (int j = 0; j < 4; j++)
                mma_bf16(acc[s][j], a[s][0], a[s][1], a[s][2], a[s][3],
                         (uint32_t)cur[j], (uint32_t)(cur[j] >> 32));
        if (ks < 7) {
#pragma unroll
            for (int j = 0; j < 4; j++) cur[j] = nxt[j];
        }
    }
}

// fused two-B pass: one A-ldmatrix stream feeds two accumulator sets (Q + K)
__device__ __forceinline__ void gemm3g2(uint32_t aBase, uint32_t aoff,
                                        const u64* __restrict__ fb1,
                                        const u64* __restrict__ fb2,
                                        float acc1[3][4][4], float acc2[3][4][4])
{
#pragma unroll
    for (int ks = 0; ks < 8; ks++) {
        u64 c1[4], c2[4];
#pragma unroll
        for (int j = 0; j < 4; j++) {
            c1[j] = __ldg(fb1 + ks * 512 + j * 32);
            c2[j] = __ldg(fb2 + ks * 512 + j * 32);
        }
        uint32_t a[3][4];
#pragma unroll
        for (int s = 0; s < 3; s++)
            ldsm_x4(a[s][0], a[s][1], a[s][2], a[s][3],
                    aBase + (uint32_t)s * (16u * RB) + aoff + (uint32_t)ks * 32u);
#pragma unroll
        for (int s = 0; s < 3; s++)
#pragma unroll
            for (int j = 0; j < 4; j++) {
                mma_bf16(acc1[s][j], a[s][0], a[s][1], a[s][2], a[s][3],
                         (uint32_t)c1[j], (uint32_t)(c1[j] >> 32));
                mma_bf16(acc2[s][j], a[s][0], a[s][1], a[s][2], a[s][3],
                         (uint32_t)c2[j], (uint32_t)(c2[j] >> 32));
            }
    }
}

// dual-A, shared-B (static hi*hi + lo*hi)
__device__ __forceinline__ void gemm3g_dual(uint32_t aBase1, uint32_t aBase2, uint32_t aoff,
                                            const u64* __restrict__ fb,
                                            float acc[3][4][4])
{
#pragma unroll
    for (int ks = 0; ks < 8; ks++) {
        u64 cur[4];
#pragma unroll
        for (int j = 0; j < 4; j++) cur[j] = __ldg(fb + ks * 512 + j * 32);
        uint32_t a1[3][4], a2[3][4];
#pragma unroll
        for (int s = 0; s < 3; s++) {
            ldsm_x4(a1[s][0], a1[s][1], a1[s][2], a1[s][3],
                    aBase1 + (uint32_t)s * (16u * RB) + aoff + (uint32_t)ks * 32u);
            ldsm_x4(a2[s][0], a2[s][1], a2[s][2], a2[s][3],
                    aBase2 + (uint32_t)s * (16u * RB) + aoff + (uint32_t)ks * 32u);
        }
#pragma unroll
        for (int s = 0; s < 3; s++)
#pragma unroll
            for (int j = 0; j < 4; j++) {
                uint32_t b0 = (uint32_t)cur[j], b1 = (uint32_t)(cur[j] >> 32);
                mma_bf16(acc[s][j], a1[s][0], a1[s][1], a1[s][2], a1[s][3], b0, b1);
                mma_bf16(acc[s][j], a2[s][0], a2[s][1], a2[s][2], a2[s][3], b0, b1);
            }
    }
}

__device__ __forceinline__ void zero_acc(float acc[3][4][4]) {
#pragma unroll
    for (int s = 0; s < 3; s++)
#pragma unroll
        for (int j = 0; j < 4; j++)
#pragma unroll
            for (int e = 0; e < 4; e++) acc[s][j][e] = 0.f;
}

__device__ __forceinline__ void build_A(const float* __restrict__ Xs,
                                        unsigned char* __restrict__ smA, int tid)
{
#pragma unroll
    for (int i = 0; i < 24; i++) {
        int p = tid + i * NTHREADS;
        int row = p >> 6, cp = p & 63;
        float2 v = *(const float2*)(Xs + row * XSTR + 2 * cp);
        *(uint32_t*)(smA + (uint32_t)row * RB + (uint32_t)cp * 4u) = bf16x2(v.x, v.y);
    }
}

// epilogue into a 272-stride buffer (K, V)
__device__ __forceinline__ void epi_kv(const float acc[3][4][4], const float* __restrict__ bias,
                                       unsigned char* __restrict__ dst, int n0, int g, int tg)
{
#pragma unroll
    for (int s = 0; s < 3; s++) {
        int r0 = 16 * s + g;
#pragma unroll
        for (int j = 0; j < 4; j++) {
            int c = n0 + 8 * j + 2 * tg;
            float bv0 = __ldg(bias + c), bv1 = __ldg(bias + c + 1);
            *(uint32_t*)(dst + (uint32_t)r0 * RB + 2u * c) =
                bf16x2(acc[s][j][0] + bv0, acc[s][j][1] + bv1);
            *(uint32_t*)(dst + (uint32_t)(r0 + 8) * RB + 2u * c) =
                bf16x2(acc[s][j][2] + bv0, acc[s][j][3] + bv1);
        }
    }
}

// epilogue into the swizzled 256-stride Q buffer
__device__ __forceinline__ void epi_q(const float acc[3][4][4], const float* __restrict__ bias,
                                      unsigned char* __restrict__ dst, int n0, int g, int tg)
{
    const uint32_t swz = (uint32_t)(g & 7) << 5;
#pragma unroll
    for (int s = 0; s < 3; s++) {
        int r0 = 16 * s + g;
#pragma unroll
        for (int j = 0; j < 4; j++) {
            int c = n0 + 8 * j + 2 * tg;
            float bv0 = __ldg(bias + c), bv1 = __ldg(bias + c + 1);
            uint32_t off = ((uint32_t)(2 * c)) ^ swz;
            *(uint32_t*)(dst + (uint32_t)r0 * QRB + off) =
                bf16x2(acc[s][j][0] + bv0, acc[s][j][1] + bv1);
            *(uint32_t*)(dst + (uint32_t)(r0 + 8) * QRB + off) =
                bf16x2(acc[s][j][2] + bv0, acc[s][j][3] + bv1);
        }
    }
}

// prep: pack 10 weight images into mma-fragment order (verified v7/v8).
__global__ void dango_prep(const float* __restrict__ Ws,
                           const float* __restrict__ Wq, const float* __restrict__ Wk,
                           const float* __restrict__ Wv, const float* __restrict__ Wo)
{
    int t = blockIdx.x * 256 + threadIdx.x;      // 0..40959
    int img  = t >> 12;
    int r    = t & 4095;
    int ks   = r >> 9;
    int j    = (r >> 5) & 15;
    int lane = r & 31;
    int n  = 8 * j + (lane >> 2);
    int k0 = 16 * ks + 2 * (lane & 3);

    const float* src;
    int lo = 0;
    if (img < 8) {
        int l = img >> 2, m = img & 3;
        src = (m == 0 ? Wq : m == 1 ? Wk : m == 2 ? Wv : Wo) + (size_t)l * H * H;
    } else {
        src = Ws;
        lo = (img == 9);
    }

    float w[4];
    w[0] = __ldg(src + (k0)     * H + n);
    w[1] = __ldg(src + (k0 + 1) * H + n);
    w[2] = __ldg(src + (k0 + 8) * H + n);
    w[3] = __ldg(src + (k0 + 9) * H + n);

    __nv_bfloat16 v[4];
#pragma unroll
    for (int i = 0; i < 4; i++) {
        if (!lo) v[i] = __float2bfloat16(w[i]);
        else {
            __nv_bfloat16 h = __float2bfloat16(w[i]);
            v[i] = __float2bfloat16(w[i] - __bfloat162float(h));
        }
    }
    uint32_t b0, b1;
    { __nv_bfloat162 p = __halves2bfloat162(v[0], v[1]); b0 = *(uint32_t*)&p; }
    { __nv_bfloat162 p = __halves2bfloat162(v[2], v[3]); b1 = *(uint32_t*)&p; }
    g_frag[t] = (u64)b0 | ((u64)b1 << 32);
}

__global__ __launch_bounds__(NTHREADS, 3)
void dango_mma(const float* __restrict__ X0,
               const float* __restrict__ bs_, const float* __restrict__ bq_,
               const float* __restrict__ bk_, const float* __restrict__ bv_,
               const float* __restrict__ bo_, const float* __restrict__ beta,
               const float* __restrict__ Wp, const float* __restrict__ bp,
               float* __restrict__ out)
{
    extern __shared__ unsigned char sm[];
    float*         Xs = (float*)(sm + XS_OFF);
    unsigned char* Ab = sm + AB_OFF;
    unsigned char* Kb = sm + KB_OFF;
    unsigned char* Vb = sm + VB_OFF;
    unsigned char* Qb = sm + QB_OFF;

    const int tid  = threadIdx.x;
    const int wid  = tid >> 5;
    const int lane = tid & 31;
    const int g    = lane >> 2;
    const int tg   = lane & 3;
    const int n0   = wid * 32;
    const int g0   = blockIdx.x * GPB;
    const size_t base = (size_t)g0 * SEQ * H;

    const uint32_t smbase = smem_u32(sm);
    const uint32_t aoff   = (uint32_t)(lane & 15) * RB + (uint32_t)(lane >> 4) * 16u;
    const uint32_t AbA = smbase + AB_OFF;
    const uint32_t KbA = smbase + KB_OFF, VbA = smbase + VB_OFF;
    const u64* fwarp = g_frag + wid * 128 + lane;   // + img*4096 + ks*512 + j*32

    // ---- init: Xs ----
#pragma unroll
    for (int i = 0; i < 12; i++) {
        int idx = tid + i * NTHREADS;        // 1536 float4
        int row = idx >> 5, c4 = idx & 31;
        float4 v = __ldg((const float4*)(X0 + base + (size_t)row * H + c4 * 4));
        *(float4*)(Xs + row * XSTR + c4 * 4) = v;
    }
    __syncthreads();

    float accA[3][4][4], accB[3][4][4];

    // ---- attention layers ----
    for (int l = 0; l < 2; l++) {
        build_A(Xs, Ab, tid);
        __syncthreads();

        // fused Q+K pass (one A stream), then V — sync-free between them
        zero_acc(accA); zero_acc(accB);
        gemm3g2(AbA, aoff, fwarp + (l * 4 + 0) * 4096, fwarp + (l * 4 + 1) * 4096,
                accA, accB);
        epi_q (accA, bq_ + l * H, Qb, n0, g, tg);
        epi_kv(accB, bk_ + l * H, Kb, n0, g, tg);

        zero_acc(accA);
        gemm3g(AbA, aoff, fwarp + (l * 4 + 2) * 4096, accA);
        epi_kv(accA, bv_ + l * H, Vb, n0, g, tg);
        __syncthreads();

        // attention (exclude-self softmax, per-head) -> Ab
        // 128 threads: (grp, head, d-half); pairwise shfl reduction.
        {
            const int grp  = tid >> 3;         // 0..15
            const int h    = (tid >> 1) & 3;   // 0..3
            const int half = tid & 1;          // 0..1
            const int rb = grp * SEQ, ho = h * 32;
            const int d0 = half * 8;           // bf16x2 index range [d0, d0+8)
            const float inv = 0.17677669529663687f;   // 1/sqrt(32)
#pragma unroll
            for (int qi = 0; qi < SEQ; qi++) {
                const int k0 = (qi == 0) ? 1 : 0;
                const int k1 = (qi == 2) ? 1 : 2;
                const int row = rb + qi;
                const uint32_t swz = (uint32_t)(row & 7) << 5;
                const unsigned char* qrow = Qb + (uint32_t)row * QRB;
                const __nv_bfloat162* ka = (const __nv_bfloat162*)(Kb + (uint32_t)(rb + k0) * RB + 2u * ho);
                const __nv_bfloat162* kb = (const __nv_bfloat162*)(Kb + (uint32_t)(rb + k1) * RB + 2u * ho);
                float s0 = 0.f, s1 = 0.f;
#pragma unroll
                for (int d = 0; d < 8; d++) {
                    int dd = d0 + d;
                    float2 qv = __bfloat1622float2(
                        *(const __nv_bfloat162*)(qrow + (((uint32_t)(64 * h + 4 * dd)) ^ swz)));
                    float2 va = __bfloat1622float2(ka[dd]);
                    float2 vb = __bfloat1622float2(kb[dd]);
                    s0 += qv.x * va.x + qv.y * va.y;
                    s1 += qv.x * vb.x + qv.y * vb.y;
                }
                s0 += __shfl_xor_sync(0xffffffffu, s0, 1);
                s1 += __shfl_xor_sync(0xffffffffu, s1, 1);
                s0 *= inv; s1 *= inv;
                float mx = fmaxf(s0, s1);
                float e0 = expf(s0 - mx), e1 = expf(s1 - mx);
                float rr = 1.0f / (e0 + e1);
                float w0 = e0 * rr, w1 = e1 * rr;
                const __nv_bfloat162* v0 = (const __nv_bfloat162*)(Vb + (uint32_t)(rb + k0) * RB + 2u * ho);
                const __nv_bfloat162* v1 = (const __nv_bfloat162*)(Vb + (uint32_t)(rb + k1) * RB + 2u * ho);
#pragma unroll
                for (int d = 0; d < 8; d++) {
                    int dd = d0 + d;
                    float2 a = __bfloat1622float2(v0[dd]);
                    float2 b = __bfloat1622float2(v1[dd]);
                    *(uint32_t*)(Ab + (uint32_t)row * RB + 2u * (ho + 2 * dd)) =
                        bf16x2(w0 * a.x + w1 * b.x, w0 * a.y + w1 * b.y);
                }
            }
        }
        __syncthreads();

        // O gemm + ReZero residual into Xs
        zero_acc(accA);
        gemm3g(AbA, aoff, fwarp + (l * 4 + 3) * 4096, accA);
        {
            const float betaL = __ldg(beta + l);
            const float* bo = bo_ + l * H;
#pragma unroll
            for (int s = 0; s < 3; s++) {
                int r0 = 16 * s + g;
#pragma unroll
                for (int j = 0; j < 4; j++) {
                    int c = n0 + 8 * j + 2 * tg;
                    float bv0 = __ldg(bo + c), bv1 = __ldg(bo + c + 1);
                    float2* p0 = (float2*)(Xs + r0 * XSTR + c);
                    float2* p1 = (float2*)(Xs + (r0 + 8) * XSTR + c);
                    float2 x0 = *p0, x1 = *p1;
                    x0.x += betaL * (accA[s][j][0] + bv0);
                    x0.y += betaL * (accA[s][j][1] + bv1);
                    x1.x += betaL * (accA[s][j][2] + bv0);
                    x1.y += betaL * (accA[s][j][3] + bv1);
                    *p0 = x0; *p1 = x1;
                }
            }
        }
        __syncthreads();
    }

    // ---- static path: relu(X0 @ Ws + bs), hi/lo split ----
#pragma unroll
    for (int i = 0; i < 24; i++) {
        int p = tid + i * NTHREADS;
        int row = p >> 6, cp = p & 63;
        float2 v = __ldg((const float2*)(X0 + base + (size_t)row * H + 2 * cp));
        __nv_bfloat16 h0 = __float2bfloat16(v.x), h1 = __float2bfloat16(v.y);
        float r0 = v.x - __bfloat162float(h0), r1 = v.y - __bfloat162float(h1);
        uint32_t off = (uint32_t)row * RB + (uint32_t)cp * 4u;
        __nv_bfloat162 hv = __halves2bfloat162(h0, h1);
        *(uint32_t*)(Kb + off) = *(uint32_t*)&hv;       // A_hi
        *(uint32_t*)(Vb + off) = bf16x2(r0, r1);        // A_lo
    }
    __syncthreads();

    zero_acc(accA);
    gemm3g_dual(KbA, VbA, aoff, fwarp + 8 * 4096, accA);   // hi*hi + lo*hi
    gemm3g(KbA, aoff, fwarp + 9 * 4096, accA);             // hi*lo

    // score: per-thread partials (reads Xs), then overlay sSc on Xs
    float pr[3][2];
#pragma unroll
    for (int s = 0; s < 3; s++) {
        int r0 = 16 * s + g;
        float sa = 0.f, sb2 = 0.f;
#pragma unroll
        for (int j = 0; j < 4; j++) {
            int c = n0 + 8 * j + 2 * tg;
            float w0 = __ldg(Wp + c), w1 = __ldg(Wp + c + 1);
            float b0 = __ldg(bs_ + c), b1 = __ldg(bs_ + c + 1);
            float st, d;
            st = fmaxf(accA[s][j][0] + b0, 0.f); d = Xs[r0 * XSTR + c] - st;           sa  += d * d * w0;
            st = fmaxf(accA[s][j][1] + b1, 0.f); d = Xs[r0 * XSTR + c + 1] - st;       sa  += d * d * w1;
            st = fmaxf(accA[s][j][2] + b0, 0.f); d = Xs[(r0 + 8) * XSTR + c] - st;     sb2 += d * d * w0;
            st = fmaxf(accA[s][j][3] + b1, 0.f); d = Xs[(r0 + 8) * XSTR + c + 1] - st; sb2 += d * d * w1;
        }
        sa  += __shfl_xor_sync(0xffffffffu, sa, 1);
        sa  += __shfl_xor_sync(0xffffffffu, sa, 2);
        sb2 += __shfl_xor_sync(0xffffffffu, sb2, 1);
        sb2 += __shfl_xor_sync(0xffffffffu, sb2, 2);
        pr[s][0] = sa; pr[s][1] = sb2;
    }
    __syncthreads();                       // all Xs reads done

    float* sSc = Xs;                       // reuse Xs[0..47]
    if (tid < TPB) sSc[tid] = __ldg(bp);
    __syncthreads();
    if (tg == 0) {
#pragma unroll
        for (int s = 0; s < 3; s++) {
            atomicAdd(&sSc[16 * s + g],     pr[s][0]);
            atomicAdd(&sSc[16 * s + g + 8], pr[s][1]);
        }
    }
    __syncthreads();

    if (tid < GPB)
        out[g0 + tid] = (sSc[tid * 3] + sSc[tid * 3 + 1] + sSc[tid * 3 + 2]) * (1.0f / 3.0f);
}

extern "C" void kernel_launch(void* const* d_in, const int* in_sizes, int n_in,
                              void* d_out, int out_size)
{
    const float* X0  = (const float*)d_in[0];
    // d_in[1] = batch (int64) — implicit: repeat(arange(G), 3)
    const float* Ws  = (const float*)d_in[2];
    const float* bs  = (const float*)d_in[3];
    const float* Wq  = (const float*)d_in[4];
    const float* bq  = (const float*)d_in[5];
    const float* Wk  = (const float*)d_in[6];
    const float* bk  = (const float*)d_in[7];
    const float* Wv  = (const float*)d_in[8];
    const float* bv  = (const float*)d_in[9];
    const float* Wo  = (const float*)d_in[10];
    const float* bo  = (const float*)d_in[11];
    const float* bet = (const float*)d_in[12];
    const float* Wp  = (const float*)d_in[13];
    const float* bp  = (const float*)d_in[14];
    float* out = (float*)d_out;

    dango_prep<<<160, 256>>>(Ws, Wq, Wk, Wv, Wo);

    cudaFuncSetAttribute(dango_mma, cudaFuncAttributeMaxDynamicSharedMemorySize, SMEM_SZ);
    dango_mma<<<GROUPS / GPB, NTHREADS, SMEM_SZ>>>(
        X0, bs, bq, bk, bv, bo, bet, Wp, bp, out);
}

// round 16
// speedup vs baseline: 1.1814x; 1.1814x over previous
#include <cuda_runtime.h>
#include <cuda_bf16.h>
#include <cstdint>

// ---------------------------------------------------------------------------
// GeneInteractionDango v15: GPB=32 (96 rows), 4 warps in a 2x2 grid:
// warp = (m-half: 3 stripes of m16) x (n-half: n64). Each A row is read by
// only 2 warps (vs 4 in v8) -> A-LDSM traffic halved; all 4 SMSPs used.
// 1 block/SM (153.6KB smem), ~full register budget, no spills.
// B operands pre-packed as mma fragments in global (LDG from L2, no smem).
// Static relu(X0@Ws+bs) via 3 accumulated hi/lo bf16 passes.
// ---------------------------------------------------------------------------

#define GROUPS   131072
#define SEQ      3
#define H        128
#define GPB      32
#define TPB      96
#define NTHREADS 128

#define XSTR     132      // f32 row stride (words)
#define RB       272u     // bf16 row stride bytes (ldsm-safe)
#define QRB      256u     // Qb row stride bytes (swizzled, non-ldsm)

// smem byte offsets (total 153600)
#define XS_OFF   0        // f32 [96][132] = 50688 (head reused as sSc)
#define AB_OFF   50688    // bf16 [96][136] = 26112
#define KB_OFF   76800
#define VB_OFF   102912
#define QB_OFF   129024   // bf16 [96][128] swizzled = 24576
#define SMEM_SZ  153600

typedef unsigned long long u64;

// frag images: 0-7 = {Wq,Wk,Wv,Wo} x layer ; 8 = Ws hi ; 9 = Ws lo
// frag[((img*8 + ks)*16 + j)*32 + lane] = (b0 | b1<<32)
__device__ __align__(16) u64 g_frag[10 * 8 * 16 * 32];

__device__ __forceinline__ void mma_bf16(float* c,
                                         uint32_t a0, uint32_t a1, uint32_t a2, uint32_t a3,
                                         uint32_t b0, uint32_t b1)
{
    asm volatile(
        "mma.sync.aligned.m16n8k16.row.col.f32.bf16.bf16.f32 "
        "{%0,%1,%2,%3}, {%4,%5,%6,%7}, {%8,%9}, {%0,%1,%2,%3};"
        : "+f"(c[0]), "+f"(c[1]), "+f"(c[2]), "+f"(c[3])
        : "r"(a0), "r"(a1), "r"(a2), "r"(a3), "r"(b0), "r"(b1));
}

__device__ __forceinline__ void ldsm_x4(uint32_t& r0, uint32_t& r1, uint32_t& r2, uint32_t& r3,
                                        uint32_t addr)
{
    asm volatile("ldmatrix.sync.aligned.m8n8.x4.shared.b16 {%0,%1,%2,%3}, [%4];"
                 : "=r"(r0), "=r"(r1), "=r"(r2), "=r"(r3) : "r"(addr));
}

__device__ __forceinline__ uint32_t smem_u32(const void* p) {
    uint32_t a;
    asm("{ .reg .u64 t; cvta.to.shared.u64 t, %1; cvt.u32.u64 %0, t; }" : "=r"(a) : "l"(p));
    return a;
}

__device__ __forceinline__ uint32_t bf16x2(float a, float b) {
    __nv_bfloat162 v = __floats2bfloat162_rn(a, b);
    return *(uint32_t*)&v;
}

// [48x128]@[128x64] per warp: A (3 stripes) via ldmatrix, B (8 j-tiles) via LDG
__device__ __forceinline__ void gemm64(uint32_t aBase, uint32_t aoff,
                                       const u64* __restrict__ fb,
                                       float acc[3][8][4])
{
    u64 cur[8];
#pragma unroll
    for (int j = 0; j < 8; j++) cur[j] = __ldg(fb + j * 32);
#pragma unroll
    for (int ks = 0; ks < 8; ks++) {
        uint32_t a[3][4];
#pragma unroll
        for (int s = 0; s < 3; s++)
            ldsm_x4(a[s][0], a[s][1], a[s][2], a[s][3],
                    aBase + (uint32_t)s * (16u * RB) + aoff + (uint32_t)ks * 32u);
        u64 nxt[8];
        if (ks < 7) {
#pragma unroll
            for (int j = 0; j < 8; j++) nxt[j] = __ldg(fb + (ks + 1) * 512 + j * 32);
        }
#pragma unroll
        for (int s = 0; s < 3; s++)
#pragma unroll
            for (int j = 0; j < 8; j++)
                mma_bf16(acc[s][j], a[s][0], a[s][1], a[s][2], a[s][3],
                         (uint32_t)cur[j], (uint32_t)(cur[j] >> 32));
        if (ks < 7) {
#pragma unroll
            for (int j = 0; j < 8; j++) cur[j] = nxt[j];
        }
    }
}

// dual-A shared-B (static hi*hi + lo*hi)
__device__ __forceinline__ void gemm64_dual(uint32_t aBase1, uint32_t aBase2, uint32_t aoff,
                                            const u64* __restrict__ fb,
                                            float acc[3][8][4])
{
#pragma unroll
    for (int ks = 0; ks < 8; ks++) {
        u64 cur[8];
#pragma unroll
        for (int j = 0; j < 8; j++) cur[j] = __ldg(fb + ks * 512 + j * 32);
        uint32_t a1[3][4], a2[3][4];
#pragma unroll
        for (int s = 0; s < 3; s++) {
            ldsm_x4(a1[s][0], a1[s][1], a1[s][2], a1[s][3],
                    aBase1 + (uint32_t)s * (16u * RB) + aoff + (uint32_t)ks * 32u);
            ldsm_x4(a2[s][0], a2[s][1], a2[s][2], a2[s][3],
                    aBase2 + (uint32_t)s * (16u * RB) + aoff + (uint32_t)ks * 32u);
        }
#pragma unroll
        for (int s = 0; s < 3; s++)
#pragma unroll
            for (int j = 0; j < 8; j++) {
                uint32_t b0 = (uint32_t)cur[j], b1 = (uint32_t)(cur[j] >> 32);
                mma_bf16(acc[s][j], a1[s][0], a1[s][1], a1[s][2], a1[s][3], b0, b1);
                mma_bf16(acc[s][j], a2[s][0], a2[s][1], a2[s][2], a2[s][3], b0, b1);
            }
    }
}

__device__ __forceinline__ void zero_acc(float acc[3][8][4]) {
#pragma unroll
    for (int s = 0; s < 3; s++)
#pragma unroll
        for (int j = 0; j < 8; j++)
#pragma unroll
            for (int e = 0; e < 4; e++) acc[s][j][e] = 0.f;
}

__device__ __forceinline__ void build_A(const float* __restrict__ Xs,
                                        unsigned char* __restrict__ smA, int tid)
{
#pragma unroll
    for (int i = 0; i < 48; i++) {
        int p = tid + i * NTHREADS;          // 6144 pairs (96 rows x 64)
        int row = p >> 6, cp = p & 63;
        float2 v = *(const float2*)(Xs + row * XSTR + 2 * cp);
        *(uint32_t*)(smA + (uint32_t)row * RB + (uint32_t)cp * 4u) = bf16x2(v.x, v.y);
    }
}

// epilogue into 272-stride buffer (K, V)
__device__ __forceinline__ void epi_kv(const float acc[3][8][4], const float* __restrict__ bias,
                                       unsigned char* __restrict__ dst,
                                       int mb, int n0, int g, int tg)
{
#pragma unroll
    for (int s = 0; s < 3; s++) {
        int r0 = mb + 16 * s + g;
#pragma unroll
        for (int j = 0; j < 8; j++) {
            int c = n0 + 8 * j + 2 * tg;
            float bv0 = __ldg(bias + c), bv1 = __ldg(bias + c + 1);
            *(uint32_t*)(dst + (uint32_t)r0 * RB + 2u * c) =
                bf16x2(acc[s][j][0] + bv0, acc[s][j][1] + bv1);
            *(uint32_t*)(dst + (uint32_t)(r0 + 8) * RB + 2u * c) =
                bf16x2(acc[s][j][2] + bv0, acc[s][j][3] + bv1);
        }
    }
}

// epilogue into the swizzled 256-stride Q buffer (rows == g mod 8)
__device__ __forceinline__ void epi_q(const float acc[3][8][4], const float* __restrict__ bias,
                                      unsigned char* __restrict__ dst,
                                      int mb, int n0, int g, int tg)
{
    const uint32_t swz = (uint32_t)(g & 7) << 5;
#pragma unroll
    for (int s = 0; s < 3; s++) {
        int r0 = mb + 16 * s + g;
#pragma unroll
        for (int j = 0; j < 8; j++) {
            int c = n0 + 8 * j + 2 * tg;
            float bv0 = __ldg(bias + c), bv1 = __ldg(bias + c + 1);
            uint32_t off = ((uint32_t)(2 * c)) ^ swz;
            *(uint32_t*)(dst + (uint32_t)r0 * QRB + off) =
                bf16x2(acc[s][j][0] + bv0, acc[s][j][1] + bv1);
            *(uint32_t*)(dst + (uint32_t)(r0 + 8) * QRB + off) =
                bf16x2(acc[s][j][2] + bv0, acc[s][j][3] + bv1);
        }
    }
}

// prep: pack 10 weight images into mma-fragment order (verified v7/v8).
__global__ void dango_prep(const float* __restrict__ Ws,
                           const float* __restrict__ Wq, const float* __restrict__ Wk,
                           const float* __restrict__ Wv, const float* __restrict__ Wo)
{
    int t = blockIdx.x * 256 + threadIdx.x;      // 0..40959
    int img  = t >> 12;
    int r    = t & 4095;
    int ks   = r >> 9;
    int j    = (r >> 5) & 15;
    int lane = r & 31;
    int n  = 8 * j + (lane >> 2);
    int k0 = 16 * ks + 2 * (lane & 3);

    const float* src;
    int lo = 0;
    if (img < 8) {
        int l = img >> 2, m = img & 3;
        src = (m == 0 ? Wq : m == 1 ? Wk : m == 2 ? Wv : Wo) + (size_t)l * H * H;
    } else {
        src = Ws;
        lo = (img == 9);
    }

    float w[4];
    w[0] = __ldg(src + (k0)     * H + n);
    w[1] = __ldg(src + (k0 + 1) * H + n);
    w[2] = __ldg(src + (k0 + 8) * H + n);
    w[3] = __ldg(src + (k0 + 9) * H + n);

    __nv_bfloat16 v[4];
#pragma unroll
    for (int i = 0; i < 4; i++) {
        if (!lo) v[i] = __float2bfloat16(w[i]);
        else {
            __nv_bfloat16 h = __float2bfloat16(w[i]);
            v[i] = __float2bfloat16(w[i] - __bfloat162float(h));
        }
    }
    uint32_t b0, b1;
    { __nv_bfloat162 p = __halves2bfloat162(v[0], v[1]); b0 = *(uint32_t*)&p; }
    { __nv_bfloat162 p = __halves2bfloat162(v[2], v[3]); b1 = *(uint32_t*)&p; }
    g_frag[t] = (u64)b0 | ((u64)b1 << 32);
}

__global__ __launch_bounds__(NTHREADS, 1)
void dango_mma(const float* __restrict__ X0,
               const float* __restrict__ bs_, const float* __restrict__ bq_,
               const float* __restrict__ bk_, const float* __restrict__ bv_,
               const float* __restrict__ bo_, const float* __restrict__ beta,
               const float* __restrict__ Wp, const float* __restrict__ bp,
               float* __restrict__ out)
{
    extern __shared__ unsigned char sm[];
    float*         Xs = (float*)(sm + XS_OFF);
    unsigned char* Ab = sm + AB_OFF;
    unsigned char* Kb = sm + KB_OFF;
    unsigned char* Vb = sm + VB_OFF;
    unsigned char* Qb = sm + QB_OFF;

    const int tid  = threadIdx.x;
    const int wid  = tid >> 5;
    const int lane = tid & 31;
    const int g    = lane >> 2;
    const int tg   = lane & 3;
    const int mh   = wid >> 1;       // m-half: 0 or 1
    const int nh   = wid & 1;        // n-half: 0 or 1
    const int mb   = mh * 48;        // row base of this warp's 3 stripes
    const int n0   = nh * 64;        // column base (n64)
    const int g0   = blockIdx.x * GPB;
    const size_t base = (size_t)g0 * SEQ * H;

    const uint32_t smbase = smem_u32(sm);
    const uint32_t aoff   = (uint32_t)(lane & 15) * RB + (uint32_t)(lane >> 4) * 16u;
    const uint32_t mbB    = (uint32_t)mb * RB;
    const uint32_t AbA = smbase + AB_OFF + mbB;
    const uint32_t KbA = smbase + KB_OFF + mbB, VbA = smbase + VB_OFF + mbB;
    const u64* fwarp = g_frag + nh * 256 + lane;   // + img*4096 + ks*512 + j*32

    // ---- init: Xs ----
#pragma unroll
    for (int i = 0; i < 24; i++) {
        int idx = tid + i * NTHREADS;        // 3072 float4 (96 rows x 32)
        int row = idx >> 5, c4 = idx & 31;
        float4 v = __ldg((const float4*)(X0 + base + (size_t)row * H + c4 * 4));
        *(float4*)(Xs + row * XSTR + c4 * 4) = v;
    }
    __syncthreads();

    float acc[3][8][4];

    // ---- attention layers ----
    for (int l = 0; l < 2; l++) {
        build_A(Xs, Ab, tid);
        __syncthreads();

        // Q, K, V back-to-back, sync-free (private output buffers)
        zero_acc(acc);
        gemm64(AbA, aoff, fwarp + (l * 4 + 0) * 4096, acc);
        epi_q(acc, bq_ + l * H, Qb, mb, n0, g, tg);

        zero_acc(acc);
        gemm64(AbA, aoff, fwarp + (l * 4 + 1) * 4096, acc);
        epi_kv(acc, bk_ + l * H, Kb, mb, n0, g, tg);

        zero_acc(acc);
        gemm64(AbA, aoff, fwarp + (l * 4 + 2) * 4096, acc);
        epi_kv(acc, bv_ + l * H, Vb, mb, n0, g, tg);
        __syncthreads();

        // attention (exclude-self softmax, per-head) -> Ab ; all 128 threads
        {
            const int grp = tid >> 2, h = tid & 3;
            const int rb = grp * SEQ, ho = h * 32;
            const float inv = 0.17677669529663687f;   // 1/sqrt(32)
#pragma unroll
            for (int qi = 0; qi < SEQ; qi++) {
                const int k0 = (qi == 0) ? 1 : 0;
                const int k1 = (qi == 2) ? 1 : 2;
                const int row = rb + qi;
                const uint32_t swz = (uint32_t)(row & 7) << 5;
                const unsigned char* qrow = Qb + (uint32_t)row * QRB;
                const __nv_bfloat162* ka = (const __nv_bfloat162*)(Kb + (uint32_t)(rb + k0) * RB + 2u * ho);
                const __nv_bfloat162* kb = (const __nv_bfloat162*)(Kb + (uint32_t)(rb + k1) * RB + 2u * ho);
                float s0 = 0.f, s1 = 0.f;
#pragma unroll
                for (int d = 0; d < 16; d++) {
                    float2 qv = __bfloat1622float2(
                        *(const __nv_bfloat162*)(qrow + (((uint32_t)(64 * h + 4 * d)) ^ swz)));
                    float2 va = __bfloat1622float2(ka[d]);
                    float2 vb = __bfloat1622float2(kb[d]);
                    s0 += qv.x * va.x + qv.y * va.y;
                    s1 += qv.x * vb.x + qv.y * vb.y;
                }
                s0 *= inv; s1 *= inv;
                float mx = fmaxf(s0, s1);
                float e0 = expf(s0 - mx), e1 = expf(s1 - mx);
                float rr = 1.0f / (e0 + e1);
                float w0 = e0 * rr, w1 = e1 * rr;
                const __nv_bfloat162* v0 = (const __nv_bfloat162*)(Vb + (uint32_t)(rb + k0) * RB + 2u * ho);
                const __nv_bfloat162* v1 = (const __nv_bfloat162*)(Vb + (uint32_t)(rb + k1) * RB + 2u * ho);
#pragma unroll
                for (int d = 0; d < 16; d++) {
                    float2 a = __bfloat1622float2(v0[d]);
                    float2 b = __bfloat1622float2(v1[d]);
                    *(uint32_t*)(Ab + (uint32_t)row * RB + 2u * (ho + 2 * d)) =
                        bf16x2(w0 * a.x + w1 * b.x, w0 * a.y + w1 * b.y);
                }
            }
        }
        __syncthreads();

        // O gemm + ReZero residual into Xs
        zero_acc(acc);
        gemm64(AbA, aoff, fwarp + (l * 4 + 3) * 4096, acc);
        {
            const float betaL = __ldg(beta + l);
            const float* bo = bo_ + l * H;
#pragma unroll
            for (int s = 0; s < 3; s++) {
                int r0 = mb + 16 * s + g;
#pragma unroll
                for (int j = 0; j < 8; j++) {
                    int c = n0 + 8 * j + 2 * tg;
                    float bv0 = __ldg(bo + c), bv1 = __ldg(bo + c + 1);
                    float2* p0 = (float2*)(Xs + r0 * XSTR + c);
                    float2* p1 = (float2*)(Xs + (r0 + 8) * XSTR + c);
                    float2 x0 = *p0, x1 = *p1;
                    x0.x += betaL * (acc[s][j][0] + bv0);
                    x0.y += betaL * (acc[s][j][1] + bv1);
                    x1.x += betaL * (acc[s][j][2] + bv0);
                    x1.y += betaL * (acc[s][j][3] + bv1);
                    *p0 = x0; *p1 = x1;
                }
            }
        }
        __syncthreads();
    }

    // ---- static path: relu(X0 @ Ws + bs), hi/lo split ----
#pragma unroll
    for (int i = 0; i < 48; i++) {
        int p = tid + i * NTHREADS;
        int row = p >> 6, cp = p & 63;
        float2 v = __ldg((const float2*)(X0 + base + (size_t)row * H + 2 * cp));
        __nv_bfloat16 h0 = __float2bfloat16(v.x), h1 = __float2bfloat16(v.y);
        float r0 = v.x - __bfloat162float(h0), r1 = v.y - __bfloat162float(h1);
        uint32_t off = (uint32_t)row * RB + (uint32_t)cp * 4u;
        __nv_bfloat162 hv = __halves2bfloat162(h0, h1);
        *(uint32_t*)(Kb + off) = *(uint32_t*)&hv;       // A_hi
        *(uint32_t*)(Vb + off) = bf16x2(r0, r1);        // A_lo
    }
    __syncthreads();

    zero_acc(acc);
    gemm64_dual(KbA, VbA, aoff, fwarp + 8 * 4096, acc);   // hi*hi + lo*hi
    gemm64(KbA, aoff, fwarp + 9 * 4096, acc);             // hi*lo

    // score: per-thread partials (reads Xs), then overlay sSc on Xs
    float pr[3][2];
#pragma unroll
    for (int s = 0; s < 3; s++) {
        int r0 = mb + 16 * s + g;
        float sa = 0.f, sb2 = 0.f;
#pragma unroll
        for (int j = 0; j < 8; j++) {
            int c = n0 + 8 * j + 2 * tg;
            float w0 = __ldg(Wp + c), w1 = __ldg(Wp + c + 1);
            float b0 = __ldg(bs_ + c), b1 = __ldg(bs_ + c + 1);
            float st, d;
            st = fmaxf(acc[s][j][0] + b0, 0.f); d = Xs[r0 * XSTR + c] - st;           sa  += d * d * w0;
            st = fmaxf(acc[s][j][1] + b1, 0.f); d = Xs[r0 * XSTR + c + 1] - st;       sa  += d * d * w1;
            st = fmaxf(acc[s][j][2] + b0, 0.f); d = Xs[(r0 + 8) * XSTR + c] - st;     sb2 += d * d * w0;
            st = fmaxf(acc[s][j][3] + b1, 0.f); d = Xs[(r0 + 8) * XSTR + c + 1] - st; sb2 += d * d * w1;
        }
        sa  += __shfl_xor_sync(0xffffffffu, sa, 1);
        sa  += __shfl_xor_sync(0xffffffffu, sa, 2);
        sb2 += __shfl_xor_sync(0xffffffffu, sb2, 1);
        sb2 += __shfl_xor_sync(0xffffffffu, sb2, 2);
        pr[s][0] = sa; pr[s][1] = sb2;
    }
    __syncthreads();                       // all Xs reads done

    float* sSc = Xs;                       // reuse Xs[0..95]
    if (tid < TPB) sSc[tid] = __ldg(bp);
    __syncthreads();
    if (tg == 0) {
#pragma unroll
        for (int s = 0; s < 3; s++) {
            atomicAdd(&sSc[mb + 16 * s + g],     pr[s][0]);
            atomicAdd(&sSc[mb + 16 * s + g + 8], pr[s][1]);
        }
    }
    __syncthreads();

    if (tid < GPB)
        out[g0 + tid] = (sSc[tid * 3] + sSc[tid * 3 + 1] + sSc[tid * 3 + 2]) * (1.0f / 3.0f);
}

extern "C" void kernel_launch(void* const* d_in, const int* in_sizes, int n_in,
                              void* d_out, int out_size)
{
    const float* X0  = (const float*)d_in[0];
    // d_in[1] = batch (int64) — implicit: repeat(arange(G), 3)
    const float* Ws  = (const float*)d_in[2];
    const float* bs  = (const float*)d_in[3];
    const float* Wq  = (const float*)d_in[4];
    const float* bq  = (const float*)d_in[5];
    const float* Wk  = (const float*)d_in[6];
    const float* bk  = (const float*)d_in[7];
    const float* Wv  = (const float*)d_in[8];
    const float* bv  = (const float*)d_in[9];
    const float* Wo  = (const float*)d_in[10];
    const float* bo  = (const float*)d_in[11];
    const float* bet = (const float*)d_in[12];
    const float* Wp  = (const float*)d_in[13];
    const float* bp  = (const float*)d_in[14];
    float* out = (float*)d_out;

    dango_prep<<<160, 256>>>(Ws, Wq, Wk, Wv, Wo);

    cudaFuncSetAttribute(dango_mma, cudaFuncAttributeMaxDynamicSharedMemorySize, SMEM_SZ);
    dango_mma<<<GROUPS / GPB, NTHREADS, SMEM_SZ>>>(
        X0, bs, bq, bk, bv, bo, bet, Wp, bp, out);
}

// round 17
// speedup vs baseline: 1.5544x; 1.3157x over previous
#include <cuda_runtime.h>
#include <cuda_bf16.h>
#include <cstdint>

// ---------------------------------------------------------------------------
// GeneInteractionDango v16: v15's 2x2 warp grid (A read by 2 warps, not 4)
// at TWO blocks/SM. Qb eliminated (scores computed from Q accumulators +
// warp shfl reduction; weights in 3KB sAw). Vb eliminated (V epilogue and
// attention combine done in-place on Ab). smem 105,984B -> 2 blocks/SM.
// B operands pre-packed as mma fragments in global (LDG from L2).
// ---------------------------------------------------------------------------

#define GROUPS   131072
#define SEQ      3
#define H        128
#define GPB      32
#define TPB      96
#define NTHREADS 128

#define XSTR     132      // f32 row stride (words)
#define RB       272u     // bf16 row stride bytes (ldsm-safe)

// smem byte offsets (total 105984)
#define XS_OFF   0        // f32 [96][132] = 50688 (head reused as sSc)
#define AB_OFF   50688    // bf16 [96][136] = 26112 (A image / V / attn-out)
#define KB_OFF   76800    // bf16 [96][136] = 26112 (K / static A_lo)
#define SAW_OFF  102912   // float2 [96][4] = 3072 (softmax weights)
#define SMEM_SZ  105984

typedef unsigned long long u64;

// frag images: 0-7 = {Wq,Wk,Wv,Wo} x layer ; 8 = Ws hi ; 9 = Ws lo
// frag[((img*8 + ks)*16 + j)*32 + lane] = (b0 | b1<<32)
__device__ __align__(16) u64 g_frag[10 * 8 * 16 * 32];

__device__ __forceinline__ void mma_bf16(float* c,
                                         uint32_t a0, uint32_t a1, uint32_t a2, uint32_t a3,
                                         uint32_t b0, uint32_t b1)
{
    asm volatile(
        "mma.sync.aligned.m16n8k16.row.col.f32.bf16.bf16.f32 "
        "{%0,%1,%2,%3}, {%4,%5,%6,%7}, {%8,%9}, {%0,%1,%2,%3};"
        : "+f"(c[0]), "+f"(c[1]), "+f"(c[2]), "+f"(c[3])
        : "r"(a0), "r"(a1), "r"(a2), "r"(a3), "r"(b0), "r"(b1));
}

__device__ __forceinline__ void ldsm_x4(uint32_t& r0, uint32_t& r1, uint32_t& r2, uint32_t& r3,
                                        uint32_t addr)
{
    asm volatile("ldmatrix.sync.aligned.m8n8.x4.shared.b16 {%0,%1,%2,%3}, [%4];"
                 : "=r"(r0), "=r"(r1), "=r"(r2), "=r"(r3) : "r"(addr));
}

__device__ __forceinline__ uint32_t smem_u32(const void* p) {
    uint32_t a;
    asm("{ .reg .u64 t; cvta.to.shared.u64 t, %1; cvt.u32.u64 %0, t; }" : "=r"(a) : "l"(p));
    return a;
}

__device__ __forceinline__ uint32_t bf16x2(float a, float b) {
    __nv_bfloat162 v = __floats2bfloat162_rn(a, b);
    return *(uint32_t*)&v;
}

// [48x128]@[128x64] per warp: A (3 stripes) via ldmatrix, B (8 j-tiles) via LDG
__device__ __forceinline__ void gemm64(uint32_t aBase, uint32_t aoff,
                                       const u64* __restrict__ fb,
                                       float acc[3][8][4])
{
    u64 cur[8];
#pragma unroll
    for (int j = 0; j < 8; j++) cur[j] = __ldg(fb + j * 32);
#pragma unroll
    for (int ks = 0; ks < 8; ks++) {
        uint32_t a[3][4];
#pragma unroll
        for (int s = 0; s < 3; s++)
            ldsm_x4(a[s][0], a[s][1], a[s][2], a[s][3],
                    aBase + (uint32_t)s * (16u * RB) + aoff + (uint32_t)ks * 32u);
        u64 nxt[8];
        if (ks < 7) {
#pragma unroll
            for (int j = 0; j < 8; j++) nxt[j] = __ldg(fb + (ks + 1) * 512 + j * 32);
        }
#pragma unroll
        for (int s = 0; s < 3; s++)
#pragma unroll
            for (int j = 0; j < 8; j++)
                mma_bf16(acc[s][j], a[s][0], a[s][1], a[s][2], a[s][3],
                         (uint32_t)cur[j], (uint32_t)(cur[j] >> 32));
        if (ks < 7) {
#pragma unroll
            for (int j = 0; j < 8; j++) cur[j] = nxt[j];
        }
    }
}

// dual-A shared-B (static hi*hi + lo*hi)
__device__ __forceinline__ void gemm64_dual(uint32_t aBase1, uint32_t aBase2, uint32_t aoff,
                                            const u64* __restrict__ fb,
                                            float acc[3][8][4])
{
#pragma unroll
    for (int ks = 0; ks < 8; ks++) {
        u64 cur[8];
#pragma unroll
        for (int j = 0; j < 8; j++) cur[j] = __ldg(fb + ks * 512 + j * 32);
        uint32_t a1[3][4], a2[3][4];
#pragma unroll
        for (int s = 0; s < 3; s++) {
            ldsm_x4(a1[s][0], a1[s][1], a1[s][2], a1[s][3],
                    aBase1 + (uint32_t)s * (16u * RB) + aoff + (uint32_t)ks * 32u);
            ldsm_x4(a2[s][0], a2[s][1], a2[s][2], a2[s][3],
                    aBase2 + (uint32_t)s * (16u * RB) + aoff + (uint32_t)ks * 32u);
        }
#pragma unroll
        for (int s = 0; s < 3; s++)
#pragma unroll
            for (int j = 0; j < 8; j++) {
                uint32_t b0 = (uint32_t)cur[j], b1 = (uint32_t)(cur[j] >> 32);
                mma_bf16(acc[s][j], a1[s][0], a1[s][1], a1[s][2], a1[s][3], b0, b1);
                mma_bf16(acc[s][j], a2[s][0], a2[s][1], a2[s][2], a2[s][3], b0, b1);
            }
    }
}

__device__ __forceinline__ void zero_acc(float acc[3][8][4]) {
#pragma unroll
    for (int s = 0; s < 3; s++)
#pragma unroll
        for (int j = 0; j < 8; j++)
#pragma unroll
            for (int e = 0; e < 4; e++) acc[s][j][e] = 0.f;
}

__device__ __forceinline__ void build_A(const float* __restrict__ Xs,
                                        unsigned char* __restrict__ smA, int tid)
{
#pragma unroll
    for (int i = 0; i < 48; i++) {
        int p = tid + i * NTHREADS;          // 6144 pairs (96 rows x 64)
        int row = p >> 6, cp = p & 63;
        float2 v = *(const float2*)(Xs + row * XSTR + 2 * cp);
        *(uint32_t*)(smA + (uint32_t)row * RB + (uint32_t)cp * 4u) = bf16x2(v.x, v.y);
    }
}

// epilogue into 272-stride buffer (+bias, bf16)
__device__ __forceinline__ void epi_b(const float acc[3][8][4], const float* __restrict__ bias,
                                      unsigned char* __restrict__ dst,
                                      int mb, int n0, int g, int tg)
{
#pragma unroll
    for (int s = 0; s < 3; s++) {
        int r0 = mb + 16 * s + g;
#pragma unroll
        for (int j = 0; j < 8; j++) {
            int c = n0 + 8 * j + 2 * tg;
            float bv0 = __ldg(bias + c), bv1 = __ldg(bias + c + 1);
            *(uint32_t*)(dst + (uint32_t)r0 * RB + 2u * c) =
                bf16x2(acc[s][j][0] + bv0, acc[s][j][1] + bv1);
            *(uint32_t*)(dst + (uint32_t)(r0 + 8) * RB + 2u * c) =
                bf16x2(acc[s][j][2] + bv0, acc[s][j][3] + bv1);
        }
    }
}

// prep: pack 10 weight images into mma-fragment order (verified v7/v8).
__global__ void dango_prep(const float* __restrict__ Ws,
                           const float* __restrict__ Wq, const float* __restrict__ Wk,
                           const float* __restrict__ Wv, const float* __restrict__ Wo)
{
    int t = blockIdx.x * 256 + threadIdx.x;      // 0..40959
    int img  = t >> 12;
    int r    = t & 4095;
    int ks   = r >> 9;
    int j    = (r >> 5) & 15;
    int lane = r & 31;
    int n  = 8 * j + (lane >> 2);
    int k0 = 16 * ks + 2 * (lane & 3);

    const float* src;
    int lo = 0;
    if (img < 8) {
        int l = img >> 2, m = img & 3;
        src = (m == 0 ? Wq : m == 1 ? Wk : m == 2 ? Wv : Wo) + (size_t)l * H * H;
    } else {
        src = Ws;
        lo = (img == 9);
    }

    float w[4];
    w[0] = __ldg(src + (k0)     * H + n);
    w[1] = __ldg(src + (k0 + 1) * H + n);
    w[2] = __ldg(src + (k0 + 8) * H + n);
    w[3] = __ldg(src + (k0 + 9) * H + n);

    __nv_bfloat16 v[4];
#pragma unroll
    for (int i = 0; i < 4; i++) {
        if (!lo) v[i] = __float2bfloat16(w[i]);
        else {
            __nv_bfloat16 h = __float2bfloat16(w[i]);
            v[i] = __float2bfloat16(w[i] - __bfloat162float(h));
        }
    }
    uint32_t b0, b1;
    { __nv_bfloat162 p = __halves2bfloat162(v[0], v[1]); b0 = *(uint32_t*)&p; }
    { __nv_bfloat162 p = __halves2bfloat162(v[2], v[3]); b1 = *(uint32_t*)&p; }
    g_frag[t] = (u64)b0 | ((u64)b1 << 32);
}

__global__ __launch_bounds__(NTHREADS, 2)
void dango_mma(const float* __restrict__ X0,
               const float* __restrict__ bs_, const float* __restrict__ bq_,
               const float* __restrict__ bk_, const float* __restrict__ bv_,
               const float* __restrict__ bo_, const float* __restrict__ beta,
               const float* __restrict__ Wp, const float* __restrict__ bp,
               float* __restrict__ out)
{
    extern __shared__ unsigned char sm[];
    float*         Xs  = (float*)(sm + XS_OFF);
    unsigned char* Ab  = sm + AB_OFF;
    unsigned char* Kb  = sm + KB_OFF;
    float*         sAw = (float*)(sm + SAW_OFF);   // [96][4][2]

    const int tid  = threadIdx.x;
    const int wid  = tid >> 5;
    const int lane = tid & 31;
    const int g    = lane >> 2;
    const int tg   = lane & 3;
    const int mh   = wid >> 1;       // m-half
    const int nh   = wid & 1;        // n-half
    const int mb   = mh * 48;
    const int n0   = nh * 64;
    const int g0   = blockIdx.x * GPB;
    const size_t base = (size_t)g0 * SEQ * H;

    const uint32_t smbase = smem_u32(sm);
    const uint32_t aoff   = (uint32_t)(lane & 15) * RB + (uint32_t)(lane >> 4) * 16u;
    const uint32_t mbB    = (uint32_t)mb * RB;
    const uint32_t AbA = smbase + AB_OFF + mbB;
    const uint32_t KbA = smbase + KB_OFF + mbB;
    const u64* fwarp = g_frag + nh * 256 + lane;   // + img*4096 + ks*512 (+ j*32)

    // ---- init: Xs ----
#pragma unroll
    for (int i = 0; i < 24; i++) {
        int idx = tid + i * NTHREADS;        // 3072 float4 (96 rows x 32)
        int row = idx >> 5, c4 = idx & 31;
        float4 v = __ldg((const float4*)(X0 + base + (size_t)row * H + c4 * 4));
        *(float4*)(Xs + row * XSTR + c4 * 4) = v;
    }
    __syncthreads();

    float acc[3][8][4];

    // ---- attention layers ----
    for (int l = 0; l < 2; l++) {
        build_A(Xs, Ab, tid);
        __syncthreads();

        // K gemm -> Kb (must precede score computation)
        zero_acc(acc);
        gemm64(AbA, aoff, fwarp + (l * 4 + 1) * 4096, acc);
        epi_b(acc, bk_ + l * H, Kb, mb, n0, g, tg);
        __syncthreads();

        // Q gemm -> scores directly from accumulators
        zero_acc(acc);
        gemm64(AbA, aoff, fwarp + (l * 4 + 0) * 4096, acc);
        {
            const float* bq = bq_ + l * H;
            const float inv = 0.17677669529663687f;   // 1/sqrt(32)
#pragma unroll
            for (int s = 0; s < 3; s++) {
#pragma unroll
                for (int half = 0; half < 2; half++) {
                    const int row = mb + 16 * s + g + 8 * half;
                    const int qi  = row % 3;
                    const int rb  = row - qi;
                    const int k0r = rb + ((qi == 0) ? 1 : 0);
                    const int k1r = rb + ((qi == 2) ? 1 : 2);
#pragma unroll
                    for (int hl = 0; hl < 2; hl++) {
                        float d0 = 0.f, d1 = 0.f;
#pragma unroll
                        for (int jj = 0; jj < 4; jj++) {
                            const int j = 4 * hl + jj;
                            const int c = n0 + 8 * j + 2 * tg;
                            float q0 = acc[s][j][2 * half + 0] + __ldg(bq + c);
                            float q1 = acc[s][j][2 * half + 1] + __ldg(bq + c + 1);
                            float2 k0v = __bfloat1622float2(
                                *(const __nv_bfloat162*)(Kb + (uint32_t)k0r * RB + 2u * c));
                            float2 k1v = __bfloat1622float2(
                                *(const __nv_bfloat162*)(Kb + (uint32_t)k1r * RB + 2u * c));
                            d0 += q0 * k0v.x + q1 * k0v.y;
                            d1 += q0 * k1v.x + q1 * k1v.y;
                        }
                        d0 += __shfl_xor_sync(0xffffffffu, d0, 1);
                        d0 += __shfl_xor_sync(0xffffffffu, d0, 2);
                        d1 += __shfl_xor_sync(0xffffffffu, d1, 1);
                        d1 += __shfl_xor_sync(0xffffffffu, d1, 2);
                        if (tg == 0) {
                            float s0 = d0 * inv, s1 = d1 * inv;
                            float mx = fmaxf(s0, s1);
                            float e0 = expf(s0 - mx), e1 = expf(s1 - mx);
                            float rr = 1.0f / (e0 + e1);
                            const int h = 2 * nh + hl;
                            ((float2*)sAw)[row * 4 + h] = make_float2(e0 * rr, e1 * rr);
                        }
                    }
                }
            }
        }

        // V gemm (reads Ab) ... sync ... write V+bv into Ab in place
        zero_acc(acc);
        gemm64(AbA, aoff, fwarp + (l * 4 + 2) * 4096, acc);
        __syncthreads();                               // all warps done reading Ab
        epi_b(acc, bv_ + l * H, Ab, mb, n0, g, tg);
        __syncthreads();

        // attention combine in place on Ab; thread = (group, head)
        {
            const int grp = tid >> 2, h = tid & 3;
            const int rb = grp * SEQ;
            const uint32_t cb = 2u * (uint32_t)(h * 32);
            uint32_t v0[16], v1[16], v2[16];
#pragma unroll
            for (int d = 0; d < 16; d++) {
                v0[d] = *(uint32_t*)(Ab + (uint32_t)(rb)     * RB + cb + 4u * d);
                v1[d] = *(uint32_t*)(Ab + (uint32_t)(rb + 1) * RB + cb + 4u * d);
                v2[d] = *(uint32_t*)(Ab + (uint32_t)(rb + 2) * RB + cb + 4u * d);
            }
            float2 w0 = ((float2*)sAw)[(rb)     * 4 + h];   // keys 1,2
            float2 w1 = ((float2*)sAw)[(rb + 1) * 4 + h];   // keys 0,2
            float2 w2 = ((float2*)sAw)[(rb + 2) * 4 + h];   // keys 0,1
#pragma unroll
            for (int d = 0; d < 16; d++) {
                float2 a = __bfloat1622float2(*(__nv_bfloat162*)&v0[d]);
                float2 b = __bfloat1622float2(*(__nv_bfloat162*)&v1[d]);
                float2 c = __bfloat1622float2(*(__nv_bfloat162*)&v2[d]);
                *(uint32_t*)(Ab + (uint32_t)(rb)     * RB + cb + 4u * d) =
                    bf16x2(w0.x * b.x + w0.y * c.x, w0.x * b.y + w0.y * c.y);
                *(uint32_t*)(Ab + (uint32_t)(rb + 1) * RB + cb + 4u * d) =
                    bf16x2(w1.x * a.x + w1.y * c.x, w1.x * a.y + w1.y * c.y);
                *(uint32_t*)(Ab + (uint32_t)(rb + 2) * RB + cb + 4u * d) =
                    bf16x2(w2.x * a.x + w2.y * b.x, w2.x * a.y + w2.y * b.y);
            }
        }
        __syncthreads();

        // O gemm + ReZero residual into Xs
        zero_acc(acc);
        gemm64(AbA, aoff, fwarp + (l * 4 + 3) * 4096, acc);
        {
            const float betaL = __ldg(beta + l);
            const float* bo = bo_ + l * H;
#pragma unroll
            for (int s = 0; s < 3; s++) {
                int r0 = mb + 16 * s + g;
#pragma unroll
                for (int j = 0; j < 8; j++) {
                    int c = n0 + 8 * j + 2 * tg;
                    float bv0 = __ldg(bo + c), bv1 = __ldg(bo + c + 1);
                    float2* p0 = (float2*)(Xs + r0 * XSTR + c);
                    float2* p1 = (float2*)(Xs + (r0 + 8) * XSTR + c);
                    float2 x0 = *p0, x1 = *p1;
                    x0.x += betaL * (acc[s][j][0] + bv0);
                    x0.y += betaL * (acc[s][j][1] + bv1);
                    x1.x += betaL * (acc[s][j][2] + bv0);
                    x1.y += betaL * (acc[s][j][3] + bv1);
                    *p0 = x0; *p1 = x1;
                }
            }
        }
        __syncthreads();
    }

    // ---- static path: relu(X0 @ Ws + bs), hi/lo split (Ahi->Ab, Alo->Kb) ----
#pragma unroll
    for (int i = 0; i < 48; i++) {
        int p = tid + i * NTHREADS;
        int row = p >> 6, cp = p & 63;
        float2 v = __ldg((const float2*)(X0 + base + (size_t)row * H + 2 * cp));
        __nv_bfloat16 h0 = __float2bfloat16(v.x), h1 = __float2bfloat16(v.y);
        float r0 = v.x - __bfloat162float(h0), r1 = v.y - __bfloat162float(h1);
        uint32_t off = (uint32_t)row * RB + (uint32_t)cp * 4u;
        __nv_bfloat162 hv = __halves2bfloat162(h0, h1);
        *(uint32_t*)(Ab + off) = *(uint32_t*)&hv;       // A_hi
        *(uint32_t*)(Kb + off) = bf16x2(r0, r1);        // A_lo
    }
    __syncthreads();

    zero_acc(acc);
    gemm64_dual(AbA, KbA, aoff, fwarp + 8 * 4096, acc);   // hi*hi + lo*hi
    gemm64(AbA, aoff, fwarp + 9 * 4096, acc);             // hi*lo

    // score: per-thread partials (reads Xs), then overlay sSc on Xs
    float pr[3][2];
#pragma unroll
    for (int s = 0; s < 3; s++) {
        int r0 = mb + 16 * s + g;
        float sa = 0.f, sb2 = 0.f;
#pragma unroll
        for (int j = 0; j < 8; j++) {
            int c = n0 + 8 * j + 2 * tg;
            float w0 = __ldg(Wp + c), w1 = __ldg(Wp + c + 1);
            float b0 = __ldg(bs_ + c), b1 = __ldg(bs_ + c + 1);
            float st, d;
            st = fmaxf(acc[s][j][0] + b0, 0.f); d = Xs[r0 * XSTR + c] - st;           sa  += d * d * w0;
            st = fmaxf(acc[s][j][1] + b1, 0.f); d = Xs[r0 * XSTR + c + 1] - st;       sa  += d * d * w1;
            st = fmaxf(acc[s][j][2] + b0, 0.f); d = Xs[(r0 + 8) * XSTR + c] - st;     sb2 += d * d * w0;
            st = fmaxf(acc[s][j][3] + b1, 0.f); d = Xs[(r0 + 8) * XSTR + c + 1] - st; sb2 += d * d * w1;
        }
        sa  += __shfl_xor_sync(0xffffffffu, sa, 1);
        sa  += __shfl_xor_sync(0xffffffffu, sa, 2);
        sb2 += __shfl_xor_sync(0xffffffffu, sb2, 1);
        sb2 += __shfl_xor_sync(0xffffffffu, sb2, 2);
        pr[s][0] = sa; pr[s][1] = sb2;
    }
    __syncthreads();                       // all Xs reads done

    float* sSc = Xs;                       // reuse Xs[0..95]
    if (tid < TPB) sSc[tid] = __ldg(bp);
    __syncthreads();
    if (tg == 0) {
#pragma unroll
        for (int s = 0; s < 3; s++) {
            atomicAdd(&sSc[mb + 16 * s + g],     pr[s][0]);
            atomicAdd(&sSc[mb + 16 * s + g + 8], pr[s][1]);
        }
    }
    __syncthreads();

    if (tid < GPB)
        out[g0 + tid] = (sSc[tid * 3] + sSc[tid * 3 + 1] + sSc[tid * 3 + 2]) * (1.0f / 3.0f);
}

extern "C" void kernel_launch(void* const* d_in, const int* in_sizes, int n_in,
                              void* d_out, int out_size)
{
    const float* X0  = (const float*)d_in[0];
    // d_in[1] = batch (int64) — implicit: repeat(arange(G), 3)
    const float* Ws  = (const float*)d_in[2];
    const float* bs  = (const float*)d_in[3];
    const float* Wq  = (const float*)d_in[4];
    const float* bq  = (const float*)d_in[5];
    const float* Wk  = (const float*)d_in[6];
    const float* bk  = (const float*)d_in[7];
    const float* Wv  = (const float*)d_in[8];
    const float* bv  = (const float*)d_in[9];
    const float* Wo  = (const float*)d_in[10];
    const float* bo  = (const float*)d_in[11];
    const float* bet = (const float*)d_in[12];
    const float* Wp  = (const float*)d_in[13];
    const float* bp  = (const float*)d_in[14];
    float* out = (float*)d_out;

    dango_prep<<<160, 256>>>(Ws, Wq, Wk, Wv, Wo);

    cudaFuncSetAttribute(dango_mma, cudaFuncAttributeMaxDynamicSharedMemorySize, SMEM_SZ);
    dango_mma<<<GROUPS / GPB, NTHREADS, SMEM_SZ>>>(
        X0, bs, bq, bk, bv, bo, bet, Wp, bp, out);
}